// round 17
// baseline (speedup 1.0000x reference)
#include <cuda_runtime.h>
#include <cuda_fp16.h>
#include <cstdint>

#define T 4
#define BSZ 16
#define C 384
#define HW 256
#define NEXP 8
#define NCOL 1024   // T*HW columns, n = hw*4 + t
#define BM 128
#define BN 128
#define NK 12       // C / 32 (sub-chunk granularity of the precomputed layouts)
#define NTHREADS 256
// double-size chunks: 2 sub-chunks of 32 k each per buffered chunk
#define CHUNKA 5120  // words: 2 * (4 wmid * 32 lane * 20)
#define CHUNKB 4224  // words: 2 * (16 group * 132)
#define ABUF (2 * CHUNKA)
#define SMEM_BYTES ((2 * CHUNKA + 2 * CHUNKB) * 4)   // 74752 (>= 128*132*4 transpose tile)

// ---------------- device scratch (no allocations allowed) ----------------
__device__ float    g_S[BSZ * C];
__device__ float    g_logit[BSZ * NEXP];
__device__ int      g_pair_e[BSZ * 2];
__device__ float    g_pair_w[BSZ * 2];
__device__ float    g_H1[(size_t)32 * C * HW * T];      // h1 scratch [p][c][hw][t] fp32
__device__ uint32_t g_SPh[(size_t)32 * NK * 16 * 8 * 128];  // stage-1 spikes [p][kc][g][l4][w]
__device__ uint32_t g_SPh2[(size_t)32 * NK * 16 * 8 * 128]; // stage-2 spikes (written by expert1 epilogue)
__device__ uint4    g_WTh[(size_t)16 * 36 * 512];       // fp16 frag-major alpha-scaled W

// ---------------- helpers ----------------
__device__ __forceinline__ float expert_tau(int e) {
    return 1.5f + (float)e * (2.5f / 7.0f);
}
__device__ __forceinline__ void cp_async16(uint32_t smem_addr, const void* gptr) {
    asm volatile("cp.async.cg.shared.global [%0], [%1], 16;\n" :: "r"(smem_addr), "l"(gptr));
}
__device__ __forceinline__ uint32_t pack_h2(float lo, float hi) {
    uint32_t r;
    asm("cvt.rn.f16x2.f32 %0, %1, %2;" : "=r"(r) : "f"(hi), "f"(lo));
    return r;
}

// ---------------- kernel: W -> fp16 fragment-major, alpha-scaled ----------------
__global__ void wtrans_kernel(const float* __restrict__ W, const float* __restrict__ bnsg, int eoff) {
    const int bid = blockIdx.x;            // 288 = e*36 + mb*12 + kc
    const int e  = bid / 36;
    const int mb = (bid / 12) % 3;
    const int kc = bid % 12;
    const float rinv = rsqrtf(1.0f + 1e-5f);
    uint4* dst = g_WTh + (((size_t)(eoff + e) * 3 + mb) * NK + kc) * 512;
#pragma unroll
    for (int it = 0; it < 2; it++) {
        int u = threadIdx.x + it * 256;    // 0..511
        int wmid = u >> 7, lane = (u >> 2) & 31, q4 = u & 3;
        int kki = q4 >> 1, mi = q4 & 1;
        int l4 = lane >> 2, q = lane & 3;
        int m0 = mb * 128 + wmid * 32 + mi * 16 + l4;
        int k0 = kc * 32 + kki * 16 + 2 * q;
        const float* s0 = W + ((size_t)e * C + m0) * C + k0;
        float2 alo = *(const float2*)s0;
        float2 ahi = *(const float2*)(s0 + 8);
        float2 blo = *(const float2*)(s0 + 8 * C);
        float2 bhi = *(const float2*)(s0 + 8 * C + 8);
        float al0 = bnsg[e * C + m0] * rinv;
        float al1 = bnsg[e * C + m0 + 8] * rinv;
        uint4 o;
        o.x = pack_h2(alo.x * al0, alo.y * al0);
        o.y = pack_h2(blo.x * al1, blo.y * al1);
        o.z = pack_h2(ahi.x * al0, ahi.y * al0);
        o.w = pack_h2(bhi.x * al1, bhi.y * al1);
        dst[u] = o;
    }
}

// ---------------- kernel: router S[b,c] ----------------
__global__ void router_s_kernel(const float* __restrict__ x) {
    int bc = blockIdx.x;
    int b = bc / C, c = bc % C;
    int hw = threadIdx.x;
    const float* px = x + (((size_t)b) * C + c) * HW + hw;
    float v = 0.f, cnt = 0.f;
#pragma unroll
    for (int t = 0; t < T; t++) {
        float xv = px[(size_t)t * BSZ * C * HW];
        v = v + (xv - v) / 2.0f;
        float s = (v >= 1.0f) ? 1.f : 0.f;
        cnt += s;
        v = v * (1.f - s);
    }
#pragma unroll
    for (int o = 16; o > 0; o >>= 1) cnt += __shfl_down_sync(0xffffffffu, cnt, o);
    __shared__ float red[8];
    if ((hw & 31) == 0) red[hw >> 5] = cnt;
    __syncthreads();
    if (hw < 8) {
        float vv = red[hw];
#pragma unroll
        for (int o = 4; o > 0; o >>= 1) vv += __shfl_down_sync(0xffu, vv, o);
        if (hw == 0) g_S[bc] = vv;
    }
}

// ---------------- kernel: per-(b,e) logit ----------------
__global__ void routing_dot(const float* __restrict__ rW, const float* __restrict__ rb,
                            const float* __restrict__ rbs, const float* __restrict__ rbb) {
    int blk = blockIdx.x, b = blk >> 3, e = blk & 7;
    int tid = threadIdx.x;   // 128
    const float* w = rW + e * C;
    const float* s = g_S + b * C;
    float dot = 0.f;
#pragma unroll
    for (int i = 0; i < 3; i++) dot += w[tid + i * 128] * s[tid + i * 128];
#pragma unroll
    for (int o = 16; o > 0; o >>= 1) dot += __shfl_down_sync(0xffffffffu, dot, o);
    __shared__ float red[4];
    if ((tid & 31) == 0) red[tid >> 5] = dot;
    __syncthreads();
    if (tid == 0) {
        float tot = red[0] + red[1] + red[2] + red[3];
        float inv = rbs[e] * rsqrtf(1.0f + 1e-5f);
        g_logit[blk] = (tot * (1.0f / (float)NCOL) + rb[e]) * inv + rbb[e];
    }
}

// ---------------- kernel: top-2 per batch ----------------
__global__ void routing_top2() {
    int b = threadIdx.x;     // 16
    float lg[NEXP];
#pragma unroll
    for (int e = 0; e < NEXP; e++) lg[e] = g_logit[b * 8 + e];
    int i0 = 0; float l0 = lg[0];
#pragma unroll
    for (int e = 1; e < NEXP; e++) if (lg[e] > l0) { l0 = lg[e]; i0 = e; }
    int i1 = -1; float l1 = -3.4e38f;
#pragma unroll
    for (int e = 0; e < NEXP; e++) if (e != i0 && lg[e] > l1) { l1 = lg[e]; i1 = e; }
    float e1 = expf(l1 - l0);
    float denom = 1.0f + e1;
    g_pair_e[2 * b]     = i0;  g_pair_w[2 * b]     = 1.0f / denom;
    g_pair_e[2 * b + 1] = i1;  g_pair_w[2 * b + 1] = e1 / denom;
}

// ---------------- kernel: stage-1 fp16 spikes ----------------
__global__ void spike1_kernel(const float* __restrict__ x) {
    int gid = blockIdx.x * 256 + threadIdx.x;   // 0 .. 16*192*128-1
    int w = gid & 127;
    int cp = (gid >> 7) % 192;
    int b = gid / (192 * 128);
    int c0 = cp * 2;
    float tau0 = expert_tau(g_pair_e[2 * b]);
    float tau1 = expert_tau(g_pair_e[2 * b + 1]);
    float2 inA[T], inB[T];
#pragma unroll
    for (int t = 0; t < T; t++) {
        const float* px = x + (((size_t)t * BSZ + b) * C + c0) * HW + 2 * w;
        inA[t] = *(const float2*)px;
        inB[t] = *(const float2*)(px + HW);
    }
    uint32_t out0[8], out1[8];
#pragma unroll
    for (int hwi = 0; hwi < 2; hwi++) {
        float vA0 = 0.f, vB0 = 0.f, vA1 = 0.f, vB1 = 0.f;
#pragma unroll
        for (int t = 0; t < T; t++) {
            float xa = hwi ? inA[t].y : inA[t].x;
            float xb = hwi ? inB[t].y : inB[t].x;
            vA0 = vA0 + (xa - vA0) / tau0; bool sa0 = vA0 >= 1.f; vA0 = sa0 ? 0.f : vA0;
            vB0 = vB0 + (xb - vB0) / tau0; bool sb0 = vB0 >= 1.f; vB0 = sb0 ? 0.f : vB0;
            vA1 = vA1 + (xa - vA1) / tau1; bool sa1 = vA1 >= 1.f; vA1 = sa1 ? 0.f : vA1;
            vB1 = vB1 + (xb - vB1) / tau1; bool sb1 = vB1 >= 1.f; vB1 = sb1 ? 0.f : vB1;
            out0[hwi * 4 + t] = (sa0 ? 0x3C00u : 0u) | (sb0 ? 0x3C000000u : 0u);
            out1[hwi * 4 + t] = (sa1 ? 0x3C00u : 0u) | (sb1 ? 0x3C000000u : 0u);
        }
    }
    int kc = c0 >> 5;
    int cl = c0 & 31;
    int g = (cl >> 4) * 8 + ((cl >> 3) & 1) * 4 + ((cl >> 1) & 3);
    uint32_t* d0 = g_SPh + (size_t)(((2 * b) * NK + kc) * 16 + g) * (8 * 128) + w;
    uint32_t* d1 = g_SPh + (size_t)(((2 * b + 1) * NK + kc) * 16 + g) * (8 * 128) + w;
#pragma unroll
    for (int l4 = 0; l4 < 8; l4++) { d0[l4 * 128] = out0[l4]; d1[l4 * 128] = out1[l4]; }
}

// ---------------- kernel: expert GEMM stage (fp16 m16n8k16, BK=64 chunks) ----------------
// Mainloop identical to R15. Epilogue: smem transpose -> per-channel coalesced IO.
// STAGE 1 epilogue additionally runs the stage-2 LIF in registers and writes
// packed fp16x2 spike words to g_SPh2 (separate buffer -> no race with readers
// of g_SPh), eliminating the spike2 kernel entirely.
template<int STAGE>
__global__ __launch_bounds__(NTHREADS, 2)
void expert_kernel(const float* __restrict__ x,
                   const float* __restrict__ bg,
                   const float* __restrict__ bnsg,
                   const float* __restrict__ bnbg,
                   float* __restrict__ outp) {
    extern __shared__ uint32_t smw[];
    const int mb = blockIdx.y;
    const int m0 = mb * BM;
    const int n0 = blockIdx.x * BN;
    const int w0 = blockIdx.x * 16;

    const int tid  = threadIdx.x;
    const int lane = tid & 31;
    const int warp = tid >> 5;
    const int wmid = warp >> 1;
    const int wm   = wmid * 32;
    const int wn   = (warp & 1) * 64;
    const int wn8  = (warp & 1) * 8;
    const int l4   = lane >> 2;
    const int q    = lane & 3;

    const int pbase = (STAGE == 1) ? blockIdx.z : 2 * blockIdx.z;
    const int b     = (STAGE == 1) ? (pbase >> 1) : blockIdx.z;
    const int eoff  = (STAGE == 1) ? 0 : 8;
    const int KT    = (STAGE == 1) ? 6 : 12;   // BK=64 chunks
    const float rinv = rsqrtf(1.0f + 1e-5f);

    int   pe[2];
    float ppw[2];
    pe[0] = g_pair_e[pbase];  ppw[0] = g_pair_w[pbase];
    pe[1] = (STAGE == 2) ? g_pair_e[pbase + 1] : 0;
    ppw[1] = (STAGE == 2) ? g_pair_w[pbase + 1] : 0.f;

    float acc[2][8][4];
#pragma unroll
    for (int mi = 0; mi < 2; mi++)
#pragma unroll
        for (int ni = 0; ni < 8; ni++)
#pragma unroll
            for (int k = 0; k < 4; k++) acc[mi][ni][k] = 0.f;

    auto copy_tiles = [&](int kt, int s) {
        int ph = (STAGE == 2 && kt < 6) ? 1 : 0;   // stage 2: weaker pair first
        int kc0 = ((kt >= 6) ? kt - 6 : kt) * 2;
#pragma unroll
        for (int h = 0; h < 2; h++) {
            int kc = kc0 + h;
            const uint4* Asrc = g_WTh + (((size_t)(eoff + pe[ph]) * 3 + mb) * NK + kc) * 512;
            uint32_t* Asd = smw + s * CHUNKA + h * 2560;
#pragma unroll
            for (int it = 0; it < 2; it++) {
                int u = tid + it * 256;
                int wmid_ = u >> 7, lane_ = (u >> 2) & 31, q4 = u & 3;
                cp_async16((uint32_t)__cvta_generic_to_shared(
                               Asd + (wmid_ * 32 + lane_) * 20 + q4 * 4),
                           Asrc + u);
            }
            const uint32_t* gsp = (STAGE == 1) ? g_SPh : g_SPh2;
            const uint32_t* Bsrc = gsp + (size_t)((pbase + ph) * NK + kc) * (16 * 8 * 128);
            uint32_t* Bsd = smw + ABUF + s * CHUNKB + h * 2112;
#pragma unroll
            for (int it = 0; it < 2; it++) {
                int u = tid + it * 256;
                int g_ = u >> 5, l4_ = (u >> 2) & 7, wq = u & 3;
                cp_async16((uint32_t)__cvta_generic_to_shared(
                               Bsd + g_ * 132 + l4_ * 16 + wq * 4),
                           Bsrc + (size_t)(g_ * 8 + l4_) * 128 + w0 + wq * 4);
            }
        }
    };

    copy_tiles(0, 0);
    asm volatile("cp.async.commit_group;\n" ::);

    for (int kt = 0; kt < KT; kt++) {
        asm volatile("cp.async.wait_group 0;\n" ::);
        __syncthreads();
        if (kt + 1 < KT) copy_tiles(kt + 1, (kt + 1) & 1);
        asm volatile("cp.async.commit_group;\n" ::);

        const int s = kt & 1;
#pragma unroll
        for (int h = 0; h < 2; h++) {
            const uint4* Ab = (const uint4*)(smw + s * CHUNKA + h * 2560 + (wmid * 32 + lane) * 20);
            const uint32_t* Bbase = smw + ABUF + s * CHUNKB + h * 2112 + q * 132 + l4 * 16 + wn8;
#pragma unroll
            for (int kki = 0; kki < 2; kki++) {
                uint4 ua0 = Ab[kki * 2 + 0];   // mi=0
                uint4 ua1 = Ab[kki * 2 + 1];   // mi=1
                const uint32_t* bp0 = Bbase + (kki * 8) * 132;
                const uint32_t* bp1 = Bbase + (kki * 8 + 4) * 132;
                uint4 rA = *(const uint4*)bp0;
                uint4 rB = *(const uint4*)(bp0 + 4);
                uint4 sA = *(const uint4*)bp1;
                uint4 sB = *(const uint4*)(bp1 + 4);
                uint32_t b0[8] = {rA.x, rA.y, rA.z, rA.w, rB.x, rB.y, rB.z, rB.w};
                uint32_t b1[8] = {sA.x, sA.y, sA.z, sA.w, sB.x, sB.y, sB.z, sB.w};
#pragma unroll
                for (int ni = 0; ni < 8; ni++) {
                    asm volatile(
                        "mma.sync.aligned.m16n8k16.row.col.f32.f16.f16.f32 "
                        "{%0,%1,%2,%3}, {%4,%5,%6,%7}, {%8,%9}, {%0,%1,%2,%3};"
                        : "+f"(acc[0][ni][0]), "+f"(acc[0][ni][1]),
                          "+f"(acc[0][ni][2]), "+f"(acc[0][ni][3])
                        : "r"(ua0.x), "r"(ua0.y), "r"(ua0.z), "r"(ua0.w),
                          "r"(b0[ni]), "r"(b1[ni]));
                    asm volatile(
                        "mma.sync.aligned.m16n8k16.row.col.f32.f16.f16.f32 "
                        "{%0,%1,%2,%3}, {%4,%5,%6,%7}, {%8,%9}, {%0,%1,%2,%3};"
                        : "+f"(acc[1][ni][0]), "+f"(acc[1][ni][1]),
                          "+f"(acc[1][ni][2]), "+f"(acc[1][ni][3])
                        : "r"(ua1.x), "r"(ua1.y), "r"(ua1.z), "r"(ua1.w),
                          "r"(b0[ni]), "r"(b1[ni]));
                }
            }
        }

        if (STAGE == 2 && kt == 5) {
            float f = ppw[1] / ppw[0];
#pragma unroll
            for (int mi = 0; mi < 2; mi++)
#pragma unroll
                for (int ni = 0; ni < 8; ni++)
#pragma unroll
                    for (int k = 0; k < 4; k++) acc[mi][ni][k] *= f;
        }
    }

    // ---- epilogue: transpose acc through smem, then coalesced per-channel IO ----
    __syncthreads();                       // mainloop smem reads complete
    float* smt = (float*)smw;              // 128 rows x 132 pitch = 67584 B
#pragma unroll
    for (int mi = 0; mi < 2; mi++)
#pragma unroll
        for (int half = 0; half < 2; half++) {
            int row = wm + mi * 16 + half * 8 + l4;
#pragma unroll
            for (int ni = 0; ni < 8; ni++) {
                int col = wn + ni * 8 + q * 2;
                *(float2*)&smt[row * 132 + col] =
                    make_float2(acc[mi][ni][half * 2 + 0], acc[mi][ni][half * 2 + 1]);
            }
        }
    __syncthreads();

    const int ol = tid >> 1;               // output channel (local)
    const int ch = tid & 1;                // n half (64 n each)
    const int o  = m0 + ol;
    const float* srow = smt + ol * 132 + ch * 64;
    const int hwb = (n0 + ch * 64) >> 2;   // 16 hw per thread

    if (STAGE == 1) {
        int e = pe[0];
        float alpha = bnsg[e * C + o] * rinv;
        float beta  = bg[e * C + o] * alpha + bnbg[e * C + o];
        const float tau2 = expert_tau(e);  // stage-2 LIF tau (same expert)
        // spike destination for channel pair (o&~1, o|1)
        const int c0 = o & ~1;
        const int kcsp = c0 >> 5;
        const int clsp = c0 & 31;
        const int gsp = (clsp >> 4) * 8 + ((clsp >> 3) & 1) * 4 + ((clsp >> 1) & 3);
        uint32_t* spbase = g_SPh2 + (size_t)((pbase * NK + kcsp) * 16 + gsp) * (8 * 128);
        const int l4base = ((tid >> 1) & 1) * 4;   // even channel writes l4 0..3, odd 4..7
#pragma unroll
        for (int cb = 0; cb < 2; cb++) {
            int hw0 = hwb + cb * 8;
            float vb[32];
#pragma unroll
            for (int i = 0; i < 8; i++) {
                float4 gg = *(const float4*)(srow + cb * 32 + i * 4);
                vb[i * 4 + 0] = gg.x; vb[i * 4 + 1] = gg.y;
                vb[i * 4 + 2] = gg.z; vb[i * 4 + 3] = gg.w;
            }
#pragma unroll
            for (int t = 0; t < T; t++) {
                const float* xs = x + (((size_t)t * BSZ + b) * C + o) * HW + hw0;
                float4 xa = *(const float4*)xs;
                float4 xc = *(const float4*)(xs + 4);
#pragma unroll
                for (int i = 0; i < 4; i++) {
                    float g0 = vb[i * 4 + t] + beta;          // acc + beta (order preserved)
                    vb[i * 4 + t] = ((const float*)&xa)[i] + g0;
                }
#pragma unroll
                for (int i = 0; i < 4; i++) {
                    float g0 = vb[(i + 4) * 4 + t] + beta;
                    vb[(i + 4) * 4 + t] = ((const float*)&xc)[i] + g0;
                }
            }
            float* hd = g_H1 + (((size_t)pbase * C + o) * HW + hw0) * T;
#pragma unroll
            for (int i = 0; i < 8; i++)
                *(float4*)(hd + i * 4) =
                    make_float4(vb[i * 4], vb[i * 4 + 1], vb[i * 4 + 2], vb[i * 4 + 3]);

            // ---- fused stage-2 LIF on vb (== g_H1 values), bit-packed ----
            // bit index i = l4sp*4 + wj;  l4sp = (j&1)*4 + t, wj = j>>1 (hw0 even)
            uint32_t mybits = 0;
#pragma unroll
            for (int j = 0; j < 8; j++) {
                float v = 0.f;
#pragma unroll
                for (int t = 0; t < T; t++) {
                    float xv = vb[j * 4 + t];
                    v = v + (xv - v) / tau2;
                    bool sp = v >= 1.f;
                    v = sp ? 0.f : v;
                    if (sp) mybits |= 1u << (((j & 1) * 4 + t) * 4 + (j >> 1));
                }
            }
            uint32_t otherbits = __shfl_xor_sync(0xffffffffu, mybits, 2);
            uint32_t lowbits  = (o & 1) ? otherbits : mybits;
            uint32_t highbits = (o & 1) ? mybits : otherbits;
            int wbase = hw0 >> 1;                      // multiple of 4
#pragma unroll
            for (int li = 0; li < 4; li++) {
                int l4sp = l4base + li;
                uint4 wd;
                wd.x = ((lowbits >> (l4sp * 4 + 0)) & 1u) * 0x3C00u | ((highbits >> (l4sp * 4 + 0)) & 1u) * 0x3C000000u;
                wd.y = ((lowbits >> (l4sp * 4 + 1)) & 1u) * 0x3C00u | ((highbits >> (l4sp * 4 + 1)) & 1u) * 0x3C000000u;
                wd.z = ((lowbits >> (l4sp * 4 + 2)) & 1u) * 0x3C00u | ((highbits >> (l4sp * 4 + 2)) & 1u) * 0x3C000000u;
                wd.w = ((lowbits >> (l4sp * 4 + 3)) & 1u) * 0x3C00u | ((highbits >> (l4sp * 4 + 3)) & 1u) * 0x3C000000u;
                *(uint4*)(spbase + l4sp * 128 + wbase) = wd;
            }
        }
    } else {
        float pw0 = ppw[0], pw1 = ppw[1];
        float a0 = bnsg[pe[0] * C + o] * rinv;
        float a1 = bnsg[pe[1] * C + o] * rinv;
        float be0 = bg[pe[0] * C + o] * a0 + bnbg[pe[0] * C + o];
        float be1 = bg[pe[1] * C + o] * a1 + bnbg[pe[1] * C + o];
#pragma unroll
        for (int cb = 0; cb < 2; cb++) {
            int hw0 = hwb + cb * 8;
            const float* h0p = g_H1 + (((size_t)(pbase + 0) * C + o) * HW + hw0) * T;
            const float* h1p = g_H1 + (((size_t)(pbase + 1) * C + o) * HW + hw0) * T;
            float vb[32];
#pragma unroll
            for (int i = 0; i < 8; i++) {
                float4 gg = *(const float4*)(srow + cb * 32 + i * 4);
                float4 h0 = *(const float4*)(h0p + i * 4);
                float4 h1 = *(const float4*)(h1p + i * 4);
#pragma unroll
                for (int jj = 0; jj < 4; jj++) {
                    // acc = S0 + (pw1/pw0)*S1 -> out = pw0*(acc + h0 + be0) + pw1*(h1 + be1)
                    vb[i * 4 + jj] = pw0 * (((const float*)&gg)[jj] + ((const float*)&h0)[jj] + be0)
                                   + pw1 * (((const float*)&h1)[jj] + be1);
                }
            }
#pragma unroll
            for (int t = 0; t < T; t++) {
                float* od = outp + (((size_t)t * BSZ + b) * C + o) * HW + hw0;
                *(float4*)od       = make_float4(vb[0 * 4 + t], vb[1 * 4 + t], vb[2 * 4 + t], vb[3 * 4 + t]);
                *(float4*)(od + 4) = make_float4(vb[4 * 4 + t], vb[5 * 4 + t], vb[6 * 4 + t], vb[7 * 4 + t]);
            }
        }
    }
}

// ---------------- launcher ----------------
extern "C" void kernel_launch(void* const* d_in, const int* in_sizes, int n_in,
                              void* d_out, int out_size) {
    const float* x   = (const float*)d_in[0];
    const float* rW  = (const float*)d_in[1];
    const float* rb  = (const float*)d_in[2];
    const float* rbs = (const float*)d_in[3];
    const float* rbb = (const float*)d_in[4];
    const float* W1  = (const float*)d_in[5];
    const float* b1  = (const float*)d_in[6];
    const float* s1  = (const float*)d_in[7];
    const float* bb1 = (const float*)d_in[8];
    const float* W2  = (const float*)d_in[9];
    const float* b2  = (const float*)d_in[10];
    const float* s2  = (const float*)d_in[11];
    const float* bb2 = (const float*)d_in[12];
    float* out = (float*)d_out;

    cudaFuncSetAttribute(expert_kernel<1>, cudaFuncAttributeMaxDynamicSharedMemorySize, SMEM_BYTES);
    cudaFuncSetAttribute(expert_kernel<2>, cudaFuncAttributeMaxDynamicSharedMemorySize, SMEM_BYTES);

    wtrans_kernel<<<288, 256>>>(W1, s1, 0);
    wtrans_kernel<<<288, 256>>>(W2, s2, 8);
    router_s_kernel<<<BSZ * C, 256>>>(x);
    routing_dot<<<128, 128>>>(rW, rb, rbs, rbb);
    routing_top2<<<1, 16>>>();

    spike1_kernel<<<(BSZ * 192 * 128) / 256, 256>>>(x);
    dim3 grid1(NCOL / BN, C / BM, 32);
    expert_kernel<1><<<grid1, NTHREADS, SMEM_BYTES>>>(x, b1, s1, bb1, out);

    dim3 grid2(NCOL / BN, C / BM, 16);
    expert_kernel<2><<<grid2, NTHREADS, SMEM_BYTES>>>(x, b2, s2, bb2, out);
}